// round 4
// baseline (speedup 1.0000x reference)
#include <cuda_runtime.h>

#define Nn   4096
#define INF_ 256
#define OUTF 64
#define KH   4
#define SEG  64
#define L2E  1.44269504088896f

// ---- scratch (no allocations allowed) ----
__device__ float g_Wh[Nn * OUTF];
__device__ float g_Wh1[Nn];
__device__ float g_Wh2[Nn];
__device__ float g_ps[SEG * KH * Nn];      // partial sums per i-segment
__device__ float g_li[KH * Nn];            // -log2(sum) per column
__device__ unsigned char g_flag[KH * Nn];  // all-masked column flag
__device__ int g_patho;

__device__ __forceinline__ float ex2(float x) {
    float r; asm("ex2.approx.f32 %0, %1;" : "=f"(r) : "f"(x)); return r;
}

// ============================================================
// K1: Wh = h @ W;  Wh1 = Wh@a[:64];  Wh2 = Wh@a[64:]
// ============================================================
__global__ void __launch_bounds__(256) k1_wh(const float* __restrict__ h,
                                             const float* __restrict__ W,
                                             const float* __restrict__ a) {
    __shared__ float sh[4][INF_];
    __shared__ float s1[4], s2[4];
    int t = threadIdx.x;
    int row0 = blockIdx.x * 4;

    for (int q = t; q < 4 * INF_; q += 256)
        sh[q >> 8][q & 255] = h[(size_t)row0 * INF_ + q];
    if (t < 4) { s1[t] = 0.f; s2[t] = 0.f; }
    if (blockIdx.x == 0 && t == 0) g_patho = 0;
    __syncthreads();

    int r = t >> 6, f = t & 63;
    float acc = 0.f;
#pragma unroll 8
    for (int c = 0; c < INF_; ++c)
        acc += sh[r][c] * W[c * OUTF + f];
    g_Wh[(size_t)(row0 + r) * OUTF + f] = acc;

    float p1 = acc * a[f];
    float p2 = acc * a[OUTF + f];
#pragma unroll
    for (int o = 16; o; o >>= 1) {
        p1 += __shfl_down_sync(0xffffffffu, p1, o);
        p2 += __shfl_down_sync(0xffffffffu, p2, o);
    }
    if ((t & 31) == 0) { atomicAdd(&s1[r], p1); atomicAdd(&s2[r], p2); }
    __syncthreads();
    if (t < 4) { g_Wh1[row0 + t] = s1[t]; g_Wh2[row0 + t] = s2[t]; }
}

// ============================================================
// K2: column sums of exp(e) over axis i (NO max tracking —
// |e| <= ~30, far inside fp32 exp range). float4 across j.
// block = (k, jt of 1024 cols, i-seg of Nn/SEG = 64 rows).
// ============================================================
__global__ void __launch_bounds__(256) k2_stats(const float* __restrict__ edge) {
    int b = blockIdx.x;
    int seg = b & (SEG - 1); b /= SEG;
    int jt = b & 3;
    int k  = b >> 2;
    int q = jt * 256 + threadIdx.x;                 // float4 column group
    const float4* base = (const float4*)(edge + (size_t)k * Nn * Nn) + q;
    float4 w2 = ((const float4*)g_Wh2)[q];

    float4 s = make_float4(0.f, 0.f, 0.f, 0.f);
    int i0 = seg * (Nn / SEG);
#pragma unroll 2
    for (int i = i0; i < i0 + Nn / SEG; ++i) {
        float4 x = base[(size_t)i * (Nn / 4)];
        float w1 = g_Wh1[i];
        if (__ballot_sync(0xffffffffu, x.x > 0.f)) {
            if (x.x > 0.f) { float tt = w1 + w2.x; float lk = fmaxf(tt, 0.2f * tt);
                             s.x += ex2(lk * x.x * L2E); }
        }
        if (__ballot_sync(0xffffffffu, x.y > 0.f)) {
            if (x.y > 0.f) { float tt = w1 + w2.y; float lk = fmaxf(tt, 0.2f * tt);
                             s.y += ex2(lk * x.y * L2E); }
        }
        if (__ballot_sync(0xffffffffu, x.z > 0.f)) {
            if (x.z > 0.f) { float tt = w1 + w2.z; float lk = fmaxf(tt, 0.2f * tt);
                             s.z += ex2(lk * x.z * L2E); }
        }
        if (__ballot_sync(0xffffffffu, x.w > 0.f)) {
            if (x.w > 0.f) { float tt = w1 + w2.w; float lk = fmaxf(tt, 0.2f * tt);
                             s.w += ex2(lk * x.w * L2E); }
        }
    }
    ((float4*)g_ps)[(size_t)seg * (KH * Nn / 4) + k * (Nn / 4) + q] = s;
}

// ============================================================
// K2b: merge segments -> li = -log2(sum). Empty column -> 1/N.
// ============================================================
__global__ void __launch_bounds__(256) k2_merge() {
    int col = blockIdx.x * 256 + threadIdx.x;
    float s = 0.f;
#pragma unroll
    for (int g = 0; g < SEG; ++g)
        s += g_ps[(size_t)g * (KH * Nn) + col];
    if (s > 0.f) {
        g_li[col] = -log2f(s);
        g_flag[col] = 0;
    } else {                               // column entirely masked
        g_li[col] = -12.0f;                // EX2(-12) = 1/4096 = 1/N
        g_flag[col] = 1;
        atomicAdd(&g_patho, 1);
    }
}

// ============================================================
// K3: 4 rows (same k) per block — w2/li loaded once per 4 rows.
// att = EX2(leaky(tt)*x*log2e + li); write att; warp bit-walk
// spmv with ballot reused as both skip-guard and walk mask.
// jwb = lane's own j base (att/flag); jwu = warp-uniform base
// (Wh gather — bit bb selects the source row).
// ============================================================
__global__ void __launch_bounds__(256) k3_attmm(const float* __restrict__ edge,
                                                float* __restrict__ att_out,
                                                float* __restrict__ out,
                                                int write_att) {
    __shared__ float s_red[4][8][OUTF];

    int t = threadIdx.x, lane = t & 31, w = t >> 5;
    int i0 = (blockIdx.x & 1023) * 4;
    int k  = blockIdx.x >> 10;

    float w1r[4];
#pragma unroll
    for (int r = 0; r < 4; ++r) w1r[r] = g_Wh1[i0 + r];

    const float4* e0 = (const float4*)(edge + ((size_t)k * Nn + i0) * Nn);
    float4* a0 = (float4*)(att_out + ((size_t)k * Nn + i0) * Nn);
    const float4* Wh2v = (const float4*)g_Wh2;
    const float4* liv  = (const float4*)(g_li + k * Nn);
    const unsigned char* flag = g_flag + k * Nn;
    const float2* whp = (const float2*)g_Wh;   // Wh row j = 32 float2
    int patho = g_patho;

    float2 acc[4];
#pragma unroll
    for (int r = 0; r < 4; ++r) acc[r] = make_float2(0.f, 0.f);

#pragma unroll
    for (int it = 0; it < 4; ++it) {
        int q = w * 128 + it * 32 + lane;          // float4 index in row
        float4 w2 = Wh2v[q];
        float4 li = liv[q];
        int jwb = q * 4;                           // lane's own j base
        int jwu = (w * 128 + it * 32) * 4;         // warp-uniform j base

#pragma unroll
        for (int r = 0; r < 4; ++r) {
            float4 x = e0[(size_t)r * (Nn / 4) + q];
            float w1 = w1r[r];
            float4 att = make_float4(0.f, 0.f, 0.f, 0.f);

#define COMP(CX, CW2, CLI, CA, CC)                                          \
            {                                                                \
                unsigned m = __ballot_sync(0xffffffffu, (CX) > 0.f);         \
                if (m) {                                                     \
                    float tt = w1 + (CW2);                                   \
                    float lk = fmaxf(tt, 0.2f * tt);                         \
                    float v  = ex2(fmaf(lk * (CX), L2E, (CLI)));             \
                    if ((CX) > 0.f) (CA) = v;                                \
                    const float2* p = whp + (size_t)(jwu + (CC)) * 32 + lane;\
                    while (m) {                                              \
                        int bb = __ffs(m) - 1; m &= m - 1;                   \
                        float aa = __shfl_sync(0xffffffffu, (CA), bb);       \
                        float2 wv = p[bb * 128];                             \
                        acc[r].x += aa * wv.x;                               \
                        acc[r].y += aa * wv.y;                               \
                    }                                                        \
                }                                                            \
            }
            COMP(x.x, w2.x, li.x, att.x, 0)
            COMP(x.y, w2.y, li.y, att.y, 1)
            COMP(x.z, w2.z, li.z, att.z, 2)
            COMP(x.w, w2.w, li.w, att.w, 3)
#undef COMP

            if (patho) {                           // never taken in practice
                if (x.x <= 0.f && flag[jwb + 0]) att.x = ex2(li.x);
                if (x.y <= 0.f && flag[jwb + 1]) att.y = ex2(li.y);
                if (x.z <= 0.f && flag[jwb + 2]) att.z = ex2(li.z);
                if (x.w <= 0.f && flag[jwb + 3]) att.w = ex2(li.w);
            }
            if (write_att) a0[(size_t)r * (Nn / 4) + q] = att;
        }
    }

#pragma unroll
    for (int r = 0; r < 4; ++r) {
        s_red[r][w][2 * lane]     = acc[r].x;
        s_red[r][w][2 * lane + 1] = acc[r].y;
    }
    __syncthreads();
    {
        int r = t >> 6, f = t & 63;
        float v = 0.f;
#pragma unroll
        for (int ww = 0; ww < 8; ++ww) v += s_red[r][ww][f];
        v = v > 0.f ? v : expm1f(v);
        out[(size_t)(i0 + r) * (KH * OUTF) + k * OUTF + f] = v;
    }
}

// ============================================================
extern "C" void kernel_launch(void* const* d_in, const int* in_sizes, int n_in,
                              void* d_out, int out_size) {
    const float *h = nullptr, *edge = nullptr, *W = nullptr, *a = nullptr;
    for (int q = 0; q < n_in; ++q) {
        switch (in_sizes[q]) {
            case Nn * INF_:    h = (const float*)d_in[q]; break;
            case INF_ * OUTF:  W = (const float*)d_in[q]; break;
            case 2 * OUTF:     a = (const float*)d_in[q]; break;
            default:
                if (in_sizes[q] == KH * Nn * Nn) edge = (const float*)d_in[q];
                break;
        }
    }
    if (!h || !edge || !W || !a) {
        if (n_in >= 4) {
            h    = (const float*)d_in[0];
            edge = (const float*)d_in[1];
            W    = (const float*)d_in[2];
            a    = (const float*)d_in[3];
        }
    }

    const long n_elu = (long)Nn * KH * OUTF;
    const long n_att = (long)KH * Nn * Nn;
    float* out = (float*)d_out;
    float* attp = out;
    int write_att = 0;
    if ((long)out_size >= n_elu + n_att) {
        attp = out + n_elu;
        write_att = 1;
    }

    k1_wh   <<<Nn / 4,         256>>>(h, W, a);
    k2_stats<<<KH * 4 * SEG,   256>>>(edge);
    k2_merge<<<KH * Nn / 256,  256>>>();
    k3_attmm<<<KH * Nn / 4,    256>>>(edge, attp, out, write_att);
}

// round 5
// speedup vs baseline: 1.5483x; 1.5483x over previous
#include <cuda_runtime.h>

#define Nn   4096
#define INF_ 256
#define OUTF 64
#define KH   4
#define SEG  64
#define L2E  1.44269504088896f

// ---- scratch (no allocations allowed) ----
__device__ float g_Wh[Nn * OUTF];
__device__ float g_Wh1[Nn];
__device__ float g_Wh2[Nn];
__device__ float g_ps[SEG * KH * Nn];      // partial sums per i-segment
__device__ float g_li[KH * Nn];            // -log2(sum) per column
__device__ unsigned char g_flag[KH * Nn];  // all-masked column flag
__device__ int g_patho;

__device__ __forceinline__ float ex2(float x) {
    float r; asm("ex2.approx.f32 %0, %1;" : "=f"(r) : "f"(x)); return r;
}

// ============================================================
// K1: Wh = h @ W;  Wh1 = Wh@a[:64];  Wh2 = Wh@a[64:]
// ============================================================
__global__ void __launch_bounds__(256) k1_wh(const float* __restrict__ h,
                                             const float* __restrict__ W,
                                             const float* __restrict__ a) {
    __shared__ float sh[4][INF_];
    __shared__ float s1[4], s2[4];
    int t = threadIdx.x;
    int row0 = blockIdx.x * 4;

    for (int q = t; q < 4 * INF_; q += 256)
        sh[q >> 8][q & 255] = h[(size_t)row0 * INF_ + q];
    if (t < 4) { s1[t] = 0.f; s2[t] = 0.f; }
    if (blockIdx.x == 0 && t == 0) g_patho = 0;
    __syncthreads();

    int r = t >> 6, f = t & 63;
    float acc = 0.f;
#pragma unroll 8
    for (int c = 0; c < INF_; ++c)
        acc += sh[r][c] * W[c * OUTF + f];
    g_Wh[(size_t)(row0 + r) * OUTF + f] = acc;

    float p1 = acc * a[f];
    float p2 = acc * a[OUTF + f];
#pragma unroll
    for (int o = 16; o; o >>= 1) {
        p1 += __shfl_down_sync(0xffffffffu, p1, o);
        p2 += __shfl_down_sync(0xffffffffu, p2, o);
    }
    if ((t & 31) == 0) { atomicAdd(&s1[r], p1); atomicAdd(&s2[r], p2); }
    __syncthreads();
    if (t < 4) { g_Wh1[row0 + t] = s1[t]; g_Wh2[row0 + t] = s2[t]; }
}

// ============================================================
// K2: column sums of exp(e) over axis i. NO max tracking
// (|e| <= ~30), NO ballots/branches — straight-line predicated.
// x==0 -> ex2(0)=1, discarded by the select; x is never negative.
// ============================================================
__global__ void __launch_bounds__(256) k2_stats(const float* __restrict__ edge) {
    int b = blockIdx.x;
    int seg = b & (SEG - 1); b /= SEG;
    int jt = b & 3;
    int k  = b >> 2;
    int q = jt * 256 + threadIdx.x;                 // float4 column group
    const float4* base = (const float4*)(edge + (size_t)k * Nn * Nn) + q;
    float4 w2 = ((const float4*)g_Wh2)[q];

    float4 s = make_float4(0.f, 0.f, 0.f, 0.f);
    int i0 = seg * (Nn / SEG);
#pragma unroll 4
    for (int i = i0; i < i0 + Nn / SEG; ++i) {
        float4 x = base[(size_t)i * (Nn / 4)];
        float w1 = g_Wh1[i];
        float tt, lk, v;
        tt = w1 + w2.x; lk = fmaxf(tt, 0.2f * tt);
        v = ex2(lk * x.x * L2E); s.x += (x.x > 0.f) ? v : 0.f;
        tt = w1 + w2.y; lk = fmaxf(tt, 0.2f * tt);
        v = ex2(lk * x.y * L2E); s.y += (x.y > 0.f) ? v : 0.f;
        tt = w1 + w2.z; lk = fmaxf(tt, 0.2f * tt);
        v = ex2(lk * x.z * L2E); s.z += (x.z > 0.f) ? v : 0.f;
        tt = w1 + w2.w; lk = fmaxf(tt, 0.2f * tt);
        v = ex2(lk * x.w * L2E); s.w += (x.w > 0.f) ? v : 0.f;
    }
    ((float4*)g_ps)[(size_t)seg * (KH * Nn / 4) + k * (Nn / 4) + q] = s;
}

// ============================================================
// K2b: merge segments -> li = -log2(sum). Empty column -> 1/N.
// ============================================================
__global__ void __launch_bounds__(256) k2_merge() {
    int col = blockIdx.x * 256 + threadIdx.x;
    float s = 0.f;
#pragma unroll
    for (int g = 0; g < SEG; ++g)
        s += g_ps[(size_t)g * (KH * Nn) + col];
    if (s > 0.f) {
        g_li[col] = -log2f(s);
        g_flag[col] = 0;
    } else {                               // column entirely masked
        g_li[col] = -12.0f;                // EX2(-12) = 1/4096 = 1/N
        g_flag[col] = 1;
        atomicAdd(&g_patho, 1);
    }
}

// ============================================================
// K3: ONE row per block (occupancy!), 8 warps x 512 j.
// att = EX2(leaky(w1+w2)*x*log2e + li); warp bit-walk spmv,
// ballot reused as skip-guard + walk mask; warp-uniform Wh base.
// ============================================================
__global__ void __launch_bounds__(256) k3_attmm(const float* __restrict__ edge,
                                                float* __restrict__ att_out,
                                                float* __restrict__ out,
                                                int write_att) {
    __shared__ float s_red[8][OUTF];

    int t = threadIdx.x, lane = t & 31, w = t >> 5;
    int i = blockIdx.x & (Nn - 1);
    int k = blockIdx.x >> 12;

    float w1 = g_Wh1[i];
    const float4* erow = (const float4*)(edge + ((size_t)k * Nn + i) * Nn);
    float4* arow = (float4*)(att_out + ((size_t)k * Nn + i) * Nn);
    const float4* Wh2v = (const float4*)g_Wh2;
    const float4* liv  = (const float4*)(g_li + k * Nn);
    const unsigned char* flag = g_flag + k * Nn;
    const float2* whp = (const float2*)g_Wh;   // Wh row j = 32 float2
    int patho = g_patho;

    float2 acc = make_float2(0.f, 0.f);

#pragma unroll
    for (int it = 0; it < 4; ++it) {
        int q = w * 128 + it * 32 + lane;          // float4 index in row
        float4 x  = erow[q];
        float4 w2 = Wh2v[q];
        float4 li = liv[q];
        int jwb = q * 4;                           // lane's own j base
        int jwu = (w * 128 + it * 32) * 4;         // warp-uniform j base
        float4 att = make_float4(0.f, 0.f, 0.f, 0.f);

#define COMP(CX, CW2, CLI, CA, CC)                                          \
        {                                                                    \
            unsigned m = __ballot_sync(0xffffffffu, (CX) > 0.f);             \
            if (m) {                                                         \
                float tt = w1 + (CW2);                                       \
                float lk = fmaxf(tt, 0.2f * tt);                             \
                float v  = ex2(fmaf(lk * (CX), L2E, (CLI)));                 \
                if ((CX) > 0.f) (CA) = v;                                    \
                const float2* p = whp + (size_t)(jwu + (CC)) * 32 + lane;    \
                while (m) {                                                  \
                    int bb = __ffs(m) - 1; m &= m - 1;                       \
                    float aa = __shfl_sync(0xffffffffu, (CA), bb);           \
                    float2 wv = p[bb * 128];                                 \
                    acc.x += aa * wv.x;                                      \
                    acc.y += aa * wv.y;                                      \
                }                                                            \
            }                                                                \
        }
        COMP(x.x, w2.x, li.x, att.x, 0)
        COMP(x.y, w2.y, li.y, att.y, 1)
        COMP(x.z, w2.z, li.z, att.z, 2)
        COMP(x.w, w2.w, li.w, att.w, 3)
#undef COMP

        if (patho) {                               // never taken in practice
            if (x.x <= 0.f && flag[jwb + 0]) att.x = ex2(li.x);
            if (x.y <= 0.f && flag[jwb + 1]) att.y = ex2(li.y);
            if (x.z <= 0.f && flag[jwb + 2]) att.z = ex2(li.z);
            if (x.w <= 0.f && flag[jwb + 3]) att.w = ex2(li.w);
        }
        if (write_att) arow[q] = att;
    }

    s_red[w][2 * lane]     = acc.x;
    s_red[w][2 * lane + 1] = acc.y;
    __syncthreads();
    if (t < OUTF) {
        float v = 0.f;
#pragma unroll
        for (int ww = 0; ww < 8; ++ww) v += s_red[ww][t];
        v = v > 0.f ? v : expm1f(v);
        out[(size_t)i * (KH * OUTF) + k * OUTF + t] = v;
    }
}

// ============================================================
extern "C" void kernel_launch(void* const* d_in, const int* in_sizes, int n_in,
                              void* d_out, int out_size) {
    const float *h = nullptr, *edge = nullptr, *W = nullptr, *a = nullptr;
    for (int q = 0; q < n_in; ++q) {
        switch (in_sizes[q]) {
            case Nn * INF_:    h = (const float*)d_in[q]; break;
            case INF_ * OUTF:  W = (const float*)d_in[q]; break;
            case 2 * OUTF:     a = (const float*)d_in[q]; break;
            default:
                if (in_sizes[q] == KH * Nn * Nn) edge = (const float*)d_in[q];
                break;
        }
    }
    if (!h || !edge || !W || !a) {
        if (n_in >= 4) {
            h    = (const float*)d_in[0];
            edge = (const float*)d_in[1];
            W    = (const float*)d_in[2];
            a    = (const float*)d_in[3];
        }
    }

    const long n_elu = (long)Nn * KH * OUTF;
    const long n_att = (long)KH * Nn * Nn;
    float* out = (float*)d_out;
    float* attp = out;
    int write_att = 0;
    if ((long)out_size >= n_elu + n_att) {
        attp = out + n_elu;
        write_att = 1;
    }

    k1_wh   <<<Nn / 4,         256>>>(h, W, a);
    k2_stats<<<KH * 4 * SEG,   256>>>(edge);
    k2_merge<<<KH * Nn / 256,  256>>>();
    k3_attmm<<<KH * Nn,        256>>>(edge, attp, out, write_att);
}